// round 7
// baseline (speedup 1.0000x reference)
#include <cuda_runtime.h>
#include <cuda_bf16.h>
#include <cstdint>
#include <cstring>

#define HIDDEN 1024
#define BB 8
#define SS 1024
#define NH 16
#define HD 64
#define SCALE 0.125f

// ---------------------------------------------------------------------------
// Scratch (no cudaMalloc allowed). All bf16 split hi/lo pairs.
// ---------------------------------------------------------------------------
#define NELEM (BB * SS * HIDDEN)     // 8M
__device__ __nv_bfloat16 g_qh[NELEM], g_ql[NELEM];
__device__ __nv_bfloat16 g_kh[NELEM], g_kl[NELEM];
__device__ __nv_bfloat16 g_vh[NELEM], g_vl[NELEM];
__device__ __nv_bfloat16 g_Wqh[HIDDEN*HIDDEN], g_Wql[HIDDEN*HIDDEN];
__device__ __nv_bfloat16 g_Wkh[HIDDEN*HIDDEN], g_Wkl[HIDDEN*HIDDEN];
__device__ __nv_bfloat16 g_Wvh[HIDDEN*HIDDEN], g_Wvl[HIDDEN*HIDDEN];
__device__ __nv_bfloat16 g_Woh[HIDDEN*HIDDEN], g_Wol[HIDDEN*HIDDEN];
__device__ __nv_bfloat16 g_Qsh[NELEM], g_Qsl[NELEM];   // [b,h,s,d]
__device__ __nv_bfloat16 g_Ksh[NELEM], g_Ksl[NELEM];   // [b,h,s,d]
__device__ __nv_bfloat16 g_Vth[NELEM], g_Vtl[NELEM];   // [b,h,d,s]
__device__ __nv_bfloat16 g_Ch[NELEM],  g_Cl[NELEM];    // ctx [b,s,1024]

__device__ __forceinline__ uint32_t b2u(__nv_bfloat162 h) {
    uint32_t u; memcpy(&u, &h, 4); return u;
}

__device__ __forceinline__ void mma16816(float* c, const uint32_t* a, const uint32_t* b) {
    asm volatile(
        "mma.sync.aligned.m16n8k16.row.col.f32.bf16.bf16.f32 "
        "{%0,%1,%2,%3}, {%4,%5,%6,%7}, {%8,%9}, {%0,%1,%2,%3};"
        : "+f"(c[0]), "+f"(c[1]), "+f"(c[2]), "+f"(c[3])
        : "r"(a[0]), "r"(a[1]), "r"(a[2]), "r"(a[3]), "r"(b[0]), "r"(b[1]));
}

__device__ __forceinline__ void ldsm_x4(uint32_t* r, uint32_t addr) {
    asm volatile("ldmatrix.sync.aligned.m8n8.x4.shared.b16 {%0,%1,%2,%3}, [%4];"
                 : "=r"(r[0]), "=r"(r[1]), "=r"(r[2]), "=r"(r[3]) : "r"(addr));
}

__device__ __forceinline__ uint32_t smem_u32(const void* p) {
    uint32_t a;
    asm("{ .reg .u64 t; cvta.to.shared.u64 t, %1; cvt.u32.u64 %0, t; }" : "=r"(a) : "l"(p));
    return a;
}

#define CP_ASYNC16(dst, src) \
    asm volatile("cp.async.cg.shared.global [%0], [%1], 16;" :: "r"(dst), "l"(src))
#define CP_COMMIT() asm volatile("cp.async.commit_group;" ::: "memory")
#define CP_WAIT(n)  asm volatile("cp.async.wait_group %0;" :: "n"(n) : "memory")

__device__ __forceinline__ void split_store2(float x, float y,
                                             __nv_bfloat16* H, __nv_bfloat16* L, size_t off) {
    __nv_bfloat162 hp = __floats2bfloat162_rn(x, y);
    float2 hf = __bfloat1622float2(hp);
    __nv_bfloat162 lp = __floats2bfloat162_rn(x - hf.x, y - hf.y);
    *(uint32_t*)(H + off) = b2u(hp);
    *(uint32_t*)(L + off) = b2u(lp);
}

__device__ __forceinline__ void split_store1(float x, __nv_bfloat16* H, __nv_bfloat16* L, size_t off) {
    __nv_bfloat16 h = __float2bfloat16(x);
    H[off] = h;
    L[off] = __float2bfloat16(x - __bfloat162float(h));
}

// ---------------------------------------------------------------------------
// One-time fp32 -> bf16 hi/lo split (all 7 tensors in one launch)
// ---------------------------------------------------------------------------
struct SplitSet { const float* X; __nv_bfloat16 *H, *L; int n4; };
struct SplitArgs { SplitSet s[7]; };

__global__ __launch_bounds__(256)
void split_all_kernel(SplitArgs a)
{
    SplitSet s = a.s[blockIdx.y];
    int i = blockIdx.x * blockDim.x + threadIdx.x;
    if (i >= s.n4) return;
    float4 v = ((const float4*)s.X)[i];
    __nv_bfloat162 h01 = __floats2bfloat162_rn(v.x, v.y);
    __nv_bfloat162 h23 = __floats2bfloat162_rn(v.z, v.w);
    float2 f01 = __bfloat1622float2(h01);
    float2 f23 = __bfloat1622float2(h23);
    __nv_bfloat162 l01 = __floats2bfloat162_rn(v.x - f01.x, v.y - f01.y);
    __nv_bfloat162 l23 = __floats2bfloat162_rn(v.z - f23.x, v.w - f23.y);
    ((uint2*)s.H)[i] = make_uint2(b2u(h01), b2u(h23));
    ((uint2*)s.L)[i] = make_uint2(b2u(l01), b2u(l23));
}

// ---------------------------------------------------------------------------
// bf16 split GEMM, cp.async double-buffered, ldmatrix fragments.
// C[m,n] = sum_k A[m,k]*W[n,k] + bias[n]  (3-pass hi/lo accumulation)
// mode 0: split-bf16 out [b,h,s,d]; mode 1: fp32 row-major; mode 2: split Vt
// ---------------------------------------------------------------------------
struct GemmSet {
    const __nv_bfloat16 *Ah, *Al, *Wh, *Wl;
    const float* bias;
    float* outF;
    __nv_bfloat16 *Oh, *Ol;
    int mode;
};
struct GemmArgs { GemmSet s[3]; };

#define G_STG 73728      // bytes per stage (4 buffers x 128 rows x 144B)
#define G_AL 18432
#define G_BH 36864
#define G_BL 55296
#define GEMM_SMEM (2 * G_STG)

__global__ __launch_bounds__(256)
void gemm_bf16_kernel(GemmArgs args)
{
    GemmSet g = args.s[blockIdx.z];
    extern __shared__ char dsm[];
    const uint32_t su = smem_u32(dsm);
    const int tid = threadIdx.x;
    const int wid = tid >> 5, lane = tid & 31;
    const int lr = lane >> 2, lc = lane & 3;
    const int n0 = blockIdx.x * 128, m0 = blockIdx.y * 128;
    const int wm = (wid >> 2) * 64;
    const int wn = (wid & 3) * 32;

    // ldmatrix lane address selectors
    const int aRow = lane & 15;
    const int aK   = (lane >> 4) << 4;
    const int bRow = (lane & 7) + ((lane >> 4) << 3);
    const int bK   = ((lane >> 3) & 1) << 4;

    float acc[4][4][4];
#pragma unroll
    for (int i = 0; i < 4; i++)
#pragma unroll
        for (int j = 0; j < 4; j++)
#pragma unroll
            for (int r = 0; r < 4; r++) acc[i][j][r] = 0.f;

#define G_LOAD(s, kt) do { \
    uint32_t base = su + (s) * G_STG; \
    _Pragma("unroll") \
    for (int li = 0; li < 4; li++) { \
        int idx = tid + li * 256; \
        int row = idx >> 3, seg = idx & 7; \
        uint32_t d0 = base + row * 144 + seg * 16; \
        CP_ASYNC16(d0,        g.Ah + (size_t)(m0 + row) * HIDDEN + (kt) * 64 + seg * 8); \
        CP_ASYNC16(d0 + G_AL, g.Al + (size_t)(m0 + row) * HIDDEN + (kt) * 64 + seg * 8); \
        CP_ASYNC16(d0 + G_BH, g.Wh + (size_t)(n0 + row) * HIDDEN + (kt) * 64 + seg * 8); \
        CP_ASYNC16(d0 + G_BL, g.Wl + (size_t)(n0 + row) * HIDDEN + (kt) * 64 + seg * 8); \
    } \
} while (0)

    G_LOAD(0, 0);
    CP_COMMIT();

    for (int kt = 0; kt < 16; kt++) {
        if (kt < 15) {
            G_LOAD((kt + 1) & 1, kt + 1);
            CP_COMMIT();
            CP_WAIT(1);
        } else {
            CP_WAIT(0);
        }
        __syncthreads();

        const uint32_t sA = su + (kt & 1) * G_STG;
        const uint32_t sB = sA + G_BH;

#pragma unroll
        for (int ks = 0; ks < 4; ks++) {
            const uint32_t kb = ks * 32;
            uint32_t Af[4][8];
#pragma unroll
            for (int i = 0; i < 4; i++) {
                uint32_t addr = sA + (wm + i * 16 + aRow) * 144 + kb + aK;
                ldsm_x4(&Af[i][0], addr);
                ldsm_x4(&Af[i][4], addr + G_AL);
            }
#pragma unroll
            for (int jp = 0; jp < 2; jp++) {
                uint32_t Bh4[4], Bl4[4];
                uint32_t baddr = sB + (wn + jp * 16 + bRow) * 144 + kb + bK;
                ldsm_x4(Bh4, baddr);
                ldsm_x4(Bl4, baddr + (G_BL - G_BH));
#pragma unroll
                for (int i = 0; i < 4; i++) {
#pragma unroll
                    for (int t = 0; t < 2; t++) {
                        int jn = jp * 2 + t;
                        mma16816(acc[i][jn], &Af[i][0], &Bh4[t * 2]);
                        mma16816(acc[i][jn], &Af[i][0], &Bl4[t * 2]);
                        mma16816(acc[i][jn], &Af[i][4], &Bh4[t * 2]);
                    }
                }
            }
        }
        __syncthreads();
    }

#pragma unroll
    for (int i = 0; i < 4; i++) {
#pragma unroll
        for (int jn = 0; jn < 4; jn++) {
            int row = m0 + wm + i * 16 + lr;
            int row8 = row + 8;
            int col = n0 + wn + jn * 8 + lc * 2;
            float x0 = acc[i][jn][0] + g.bias[col], y0 = acc[i][jn][1] + g.bias[col + 1];
            float x1 = acc[i][jn][2] + g.bias[col], y1 = acc[i][jn][3] + g.bias[col + 1];
            if (g.mode == 0) {
                int b0_ = row >> 10, s0_ = row & 1023;
                int b1_ = row8 >> 10, s1_ = row8 & 1023;
                int h = col >> 6, d = col & 63;
                split_store2(x0, y0, g.Oh, g.Ol, (((size_t)(b0_ * NH + h)) * SS + s0_) * HD + d);
                split_store2(x1, y1, g.Oh, g.Ol, (((size_t)(b1_ * NH + h)) * SS + s1_) * HD + d);
            } else if (g.mode == 1) {
                *(float2*)(g.outF + (size_t)row * HIDDEN + col) = make_float2(x0, y0);
                *(float2*)(g.outF + (size_t)row8 * HIDDEN + col) = make_float2(x1, y1);
            } else {
                int b0_ = row >> 10, s0_ = row & 1023;
                int s1_ = row8 & 1023;
                int h = col >> 6, d = col & 63;
                size_t base = (size_t)(b0_ * NH + h) * HD;
                split_store1(x0, g.Oh, g.Ol, (base + d) * SS + s0_);
                split_store1(y0, g.Oh, g.Ol, (base + d + 1) * SS + s0_);
                split_store1(x1, g.Oh, g.Ol, (base + d) * SS + s1_);
                split_store1(y1, g.Oh, g.Ol, (base + d + 1) * SS + s1_);
            }
        }
    }
}

// ---------------------------------------------------------------------------
// Tensor-core flash attention, pre-split bf16 inputs, cp.async pipelined K/V,
// ldmatrix fragments. 1 CTA per (b, h, 128 q rows); 8 warps x 16 rows.
// ---------------------------------------------------------------------------
#define F_QH 0
#define F_QL 18432
#define F_K(s) (36864 + (s) * 36864)    // KL at +18432
#define F_V(s) (110592 + (s) * 34816)   // VL at +17408
#define F_ZS 180224
#define FLASH_SMEM (F_ZS + 1152 * 4)

__global__ __launch_bounds__(256)
void flash_tc_kernel(const __nv_bfloat16* __restrict__ Qhg, const __nv_bfloat16* __restrict__ Qlg,
                     const __nv_bfloat16* __restrict__ Khg, const __nv_bfloat16* __restrict__ Klg,
                     const __nv_bfloat16* __restrict__ Vthg, const __nv_bfloat16* __restrict__ Vtlg,
                     const float* __restrict__ attn_bias, const float* __restrict__ zoom,
                     __nv_bfloat16* __restrict__ Ch, __nv_bfloat16* __restrict__ Cl)
{
    extern __shared__ char sm[];
    const uint32_t su = smem_u32(sm);
    float* zs = (float*)(sm + F_ZS);

    const int tid = threadIdx.x;
    const int wid = tid >> 5, lane = tid & 31;
    const int lr = lane >> 2, lc = lane & 3;
    const int wq = wid * 16;
    const int qt = blockIdx.x, h = blockIdx.y, b = blockIdx.z;
    const int qr0 = qt * 128;

    const int aRow = lane & 15;
    const int aK   = (lane >> 4) << 4;
    const int bRow = (lane & 7) + ((lane >> 4) << 3);
    const int bK   = ((lane >> 3) & 1) << 4;

    const __nv_bfloat16* gQh  = Qhg + (((size_t)(b * NH + h)) * SS + qr0) * HD;
    const __nv_bfloat16* gQl  = Qlg + (((size_t)(b * NH + h)) * SS + qr0) * HD;
    const __nv_bfloat16* gKh  = Khg + ((size_t)(b * NH + h)) * SS * HD;
    const __nv_bfloat16* gKl  = Klg + ((size_t)(b * NH + h)) * SS * HD;
    const __nv_bfloat16* gVth = Vthg + ((size_t)(b * NH + h)) * HD * SS;
    const __nv_bfloat16* gVtl = Vtlg + ((size_t)(b * NH + h)) * HD * SS;
    const float* gB = attn_bias + (size_t)b * SS * SS;

#define F_LOAD(s, t0) do { \
    _Pragma("unroll") \
    for (int li = 0; li < 4; li++) { \
        int idx = tid + li * 256; \
        int row = idx >> 3, seg = idx & 7; \
        uint32_t dk = su + F_K(s) + row * 144 + seg * 16; \
        CP_ASYNC16(dk,         gKh + (size_t)((t0) + row) * HD + seg * 8); \
        CP_ASYNC16(dk + 18432, gKl + (size_t)((t0) + row) * HD + seg * 8); \
    } \
    _Pragma("unroll") \
    for (int li = 0; li < 4; li++) { \
        int idx = tid + li * 256; \
        int d = idx >> 4, seg = idx & 15; \
        uint32_t dv = su + F_V(s) + d * 272 + seg * 16; \
        CP_ASYNC16(dv,         gVth + (size_t)d * SS + (t0) + seg * 8); \
        CP_ASYNC16(dv + 17408, gVtl + (size_t)d * SS + (t0) + seg * 8); \
    } \
} while (0)

    F_LOAD(0, 0);
    CP_COMMIT();

    for (int u = tid; u < 1152; u += 256)
        zs[u] = (qr0 + u < 2047) ? zoom[qr0 + u] : 0.f;
#pragma unroll
    for (int li = 0; li < 4; li++) {
        int idx = tid + li * 256;
        int row = idx >> 3, seg = idx & 7;
        *(uint4*)(sm + F_QH + row * 144 + seg * 16) = *(const uint4*)(gQh + row * HD + seg * 8);
        *(uint4*)(sm + F_QL + row * 144 + seg * 16) = *(const uint4*)(gQl + row * HD + seg * 8);
    }

    float accO[8][4];
#pragma unroll
    for (int nt = 0; nt < 8; nt++)
#pragma unroll
        for (int r = 0; r < 4; r++) accO[nt][r] = 0.f;
    float mi0 = -3.0e38f, mi1 = -3.0e38f, li0 = 0.f, li1 = 0.f;

    for (int kt = 0; kt < 8; kt++) {
        const int t0 = kt * 128;
        if (kt < 7) {
            F_LOAD((kt + 1) & 1, t0 + 128);
            CP_COMMIT();
            CP_WAIT(1);
        } else {
            CP_WAIT(0);
        }
        __syncthreads();

        const uint32_t sK = su + F_K(kt & 1);
        const uint32_t sV = su + F_V(kt & 1);

        // S = Q.K^T : warp computes 16 x 128
        float sc[16][4];
#pragma unroll
        for (int nt = 0; nt < 16; nt++)
#pragma unroll
            for (int r = 0; r < 4; r++) sc[nt][r] = 0.f;

#pragma unroll
        for (int ks = 0; ks < 4; ks++) {
            const uint32_t kb = ks * 32;
            uint32_t Qh4[4], Ql4[4];
            uint32_t qaddr = su + F_QH + (wq + aRow) * 144 + kb + aK;
            ldsm_x4(Qh4, qaddr);
            ldsm_x4(Ql4, qaddr + F_QL);
#pragma unroll
            for (int tp = 0; tp < 8; tp++) {
                uint32_t Kh4[4], Kl4[4];
                uint32_t kaddr = sK + (tp * 16 + bRow) * 144 + kb + bK;
                ldsm_x4(Kh4, kaddr);
                ldsm_x4(Kl4, kaddr + 18432);
#pragma unroll
                for (int t = 0; t < 2; t++) {
                    int nt = tp * 2 + t;
                    mma16816(sc[nt], Qh4, &Kh4[t * 2]);
                    mma16816(sc[nt], Qh4, &Kl4[t * 2]);
                    mma16816(sc[nt], Ql4, &Kh4[t * 2]);
                }
            }
        }

        // scale + biases, online softmax
        const int row_l0 = wq + lr;
        float mx0 = -3.0e38f, mx1 = -3.0e38f;
#pragma unroll
        for (int nt = 0; nt < 16; nt++) {
            int keyg = t0 + nt * 8 + lc * 2;
            const float* bp = gB + (size_t)(qr0 + row_l0) * SS + keyg;
            float2 bv0 = *(const float2*)bp;
            float2 bv1 = *(const float2*)(bp + 8 * SS);
            int u0 = row_l0 - keyg + 1023;
            sc[nt][0] = fmaf(sc[nt][0], SCALE, bv0.x + zs[u0]);
            sc[nt][1] = fmaf(sc[nt][1], SCALE, bv0.y + zs[u0 - 1]);
            sc[nt][2] = fmaf(sc[nt][2], SCALE, bv1.x + zs[u0 + 8]);
            sc[nt][3] = fmaf(sc[nt][3], SCALE, bv1.y + zs[u0 + 7]);
            mx0 = fmaxf(mx0, fmaxf(sc[nt][0], sc[nt][1]));
            mx1 = fmaxf(mx1, fmaxf(sc[nt][2], sc[nt][3]));
        }
#pragma unroll
        for (int off = 1; off <= 2; off <<= 1) {
            mx0 = fmaxf(mx0, __shfl_xor_sync(0xffffffffu, mx0, off));
            mx1 = fmaxf(mx1, __shfl_xor_sync(0xffffffffu, mx1, off));
        }
        float m0n = fmaxf(mi0, mx0), m1n = fmaxf(mi1, mx1);
        float a0 = __expf(mi0 - m0n), a1 = __expf(mi1 - m1n);
        mi0 = m0n; mi1 = m1n;
        float rs0 = 0.f, rs1 = 0.f;
#pragma unroll
        for (int nt = 0; nt < 16; nt++) {
            sc[nt][0] = __expf(sc[nt][0] - m0n);
            sc[nt][1] = __expf(sc[nt][1] - m0n);
            sc[nt][2] = __expf(sc[nt][2] - m1n);
            sc[nt][3] = __expf(sc[nt][3] - m1n);
            rs0 += sc[nt][0] + sc[nt][1];
            rs1 += sc[nt][2] + sc[nt][3];
        }
#pragma unroll
        for (int off = 1; off <= 2; off <<= 1) {
            rs0 += __shfl_xor_sync(0xffffffffu, rs0, off);
            rs1 += __shfl_xor_sync(0xffffffffu, rs1, off);
        }
        li0 = li0 * a0 + rs0;
        li1 = li1 * a1 + rs1;
#pragma unroll
        for (int nt = 0; nt < 8; nt++) {
            accO[nt][0] *= a0; accO[nt][1] *= a0;
            accO[nt][2] *= a1; accO[nt][3] *= a1;
        }

        // O += P.V  (P in registers; hi/lo split of P)
#pragma unroll
        for (int g = 0; g < 8; g++) {
            uint32_t Ph[4], Pl[4];
#pragma unroll
            for (int t = 0; t < 2; t++)
#pragma unroll
                for (int r = 0; r < 2; r++) {
                    float x = sc[2 * g + t][2 * r], y = sc[2 * g + t][2 * r + 1];
                    __nv_bfloat162 hp = __floats2bfloat162_rn(x, y);
                    float2 hf = __bfloat1622float2(hp);
                    __nv_bfloat162 lp = __floats2bfloat162_rn(x - hf.x, y - hf.y);
                    Ph[t * 2 + r] = b2u(hp);
                    Pl[t * 2 + r] = b2u(lp);
                }
            const uint32_t kbv = g * 32;
#pragma unroll
            for (int vp = 0; vp < 4; vp++) {
                uint32_t Vh4[4], Vl4[4];
                uint32_t vaddr = sV + (vp * 16 + bRow) * 272 + kbv + bK;
                ldsm_x4(Vh4, vaddr);
                ldsm_x4(Vl4, vaddr + 17408);
#pragma unroll
                for (int t = 0; t < 2; t++) {
                    int nt = vp * 2 + t;
                    mma16816(accO[nt], Ph, &Vh4[t * 2]);
                    mma16816(accO[nt], Ph, &Vl4[t * 2]);
                    mma16816(accO[nt], Pl, &Vh4[t * 2]);
                }
            }
        }
        __syncthreads();
    }

    // epilogue: normalize, write split-bf16 Ctx[b][row][h*64+d]
    float inv0 = 1.f / li0, inv1 = 1.f / li1;
    int row0 = qr0 + wq + lr;
#pragma unroll
    for (int nt = 0; nt < 8; nt++) {
        int col = h * HD + nt * 8 + lc * 2;
        split_store2(accO[nt][0] * inv0, accO[nt][1] * inv0, Ch, Cl,
                     ((size_t)(b * SS + row0)) * HIDDEN + col);
        split_store2(accO[nt][2] * inv1, accO[nt][3] * inv1, Ch, Cl,
                     ((size_t)(b * SS + row0 + 8)) * HIDDEN + col);
    }
}

extern "C" void kernel_launch(void* const* d_in, const int* in_sizes, int n_in,
                              void* d_out, int out_size)
{
    const float* q    = (const float*)d_in[0];
    const float* k    = (const float*)d_in[1];
    const float* v    = (const float*)d_in[2];
    const float* ab   = (const float*)d_in[3];
    const float* Wq   = (const float*)d_in[4];
    const float* bq   = (const float*)d_in[5];
    const float* Wk   = (const float*)d_in[6];
    const float* bk   = (const float*)d_in[7];
    const float* Wv   = (const float*)d_in[8];
    const float* bv   = (const float*)d_in[9];
    const float* Wo   = (const float*)d_in[10];
    const float* bo   = (const float*)d_in[11];
    const float* zoom = (const float*)d_in[12];

    __nv_bfloat16 *qh, *ql, *kh, *kl, *vh, *vl;
    __nv_bfloat16 *Wqh, *Wql, *Wkh, *Wkl, *Wvh, *Wvl, *Woh, *Wol;
    __nv_bfloat16 *Qsh, *Qsl, *Ksh, *Ksl, *Vth, *Vtl, *Ch, *Cl;
    cudaGetSymbolAddress((void**)&qh, g_qh);   cudaGetSymbolAddress((void**)&ql, g_ql);
    cudaGetSymbolAddress((void**)&kh, g_kh);   cudaGetSymbolAddress((void**)&kl, g_kl);
    cudaGetSymbolAddress((void**)&vh, g_vh);   cudaGetSymbolAddress((void**)&vl, g_vl);
    cudaGetSymbolAddress((void**)&Wqh, g_Wqh); cudaGetSymbolAddress((void**)&Wql, g_Wql);
    cudaGetSymbolAddress((void**)&Wkh, g_Wkh); cudaGetSymbolAddress((void**)&Wkl, g_Wkl);
    cudaGetSymbolAddress((void**)&Wvh, g_Wvh); cudaGetSymbolAddress((void**)&Wvl, g_Wvl);
    cudaGetSymbolAddress((void**)&Woh, g_Woh); cudaGetSymbolAddress((void**)&Wol, g_Wol);
    cudaGetSymbolAddress((void**)&Qsh, g_Qsh); cudaGetSymbolAddress((void**)&Qsl, g_Qsl);
    cudaGetSymbolAddress((void**)&Ksh, g_Ksh); cudaGetSymbolAddress((void**)&Ksl, g_Ksl);
    cudaGetSymbolAddress((void**)&Vth, g_Vth); cudaGetSymbolAddress((void**)&Vtl, g_Vtl);
    cudaGetSymbolAddress((void**)&Ch, g_Ch);   cudaGetSymbolAddress((void**)&Cl, g_Cl);

    cudaFuncSetAttribute(gemm_bf16_kernel,
                         cudaFuncAttributeMaxDynamicSharedMemorySize, GEMM_SMEM);
    cudaFuncSetAttribute(flash_tc_kernel,
                         cudaFuncAttributeMaxDynamicSharedMemorySize, FLASH_SMEM);

    const int WN4 = HIDDEN * HIDDEN / 4;
    SplitArgs sa = {};
    sa.s[0] = { q,  qh,  ql,  NELEM / 4 };
    sa.s[1] = { k,  kh,  kl,  NELEM / 4 };
    sa.s[2] = { v,  vh,  vl,  NELEM / 4 };
    sa.s[3] = { Wq, Wqh, Wql, WN4 };
    sa.s[4] = { Wk, Wkh, Wkl, WN4 };
    sa.s[5] = { Wv, Wvh, Wvl, WN4 };
    sa.s[6] = { Wo, Woh, Wol, WN4 };
    split_all_kernel<<<dim3(NELEM / 4 / 256, 7), 256>>>(sa);

    GemmArgs ga = {};
    ga.s[0] = { qh, ql, Wqh, Wql, bq, nullptr, Qsh, Qsl, 0 };
    ga.s[1] = { kh, kl, Wkh, Wkl, bk, nullptr, Ksh, Ksl, 0 };
    ga.s[2] = { vh, vl, Wvh, Wvl, bv, nullptr, Vth, Vtl, 2 };
    gemm_bf16_kernel<<<dim3(HIDDEN / 128, (BB * SS) / 128, 3), 256, GEMM_SMEM>>>(ga);

    dim3 gf(SS / 128, NH, BB);
    flash_tc_kernel<<<gf, 256, FLASH_SMEM>>>(Qsh, Qsl, Ksh, Ksl, Vth, Vtl, ab, zoom, Ch, Cl);

    GemmArgs go = {};
    go.s[0] = { Ch, Cl, Woh, Wol, bo, (float*)d_out, nullptr, nullptr, 1 };
    gemm_bf16_kernel<<<dim3(HIDDEN / 128, (BB * SS) / 128, 1), 256, GEMM_SMEM>>>(go);
}

// round 10
// speedup vs baseline: 1.3762x; 1.3762x over previous
#include <cuda_runtime.h>
#include <cuda_bf16.h>
#include <cstdint>
#include <cstring>

#define HIDDEN 1024
#define BB 8
#define SS 1024
#define NH 16
#define HD 64
#define SCALE 0.125f

// ---------------------------------------------------------------------------
// Scratch (no cudaMalloc allowed). All bf16 split hi/lo pairs.
// ---------------------------------------------------------------------------
#define NELEM (BB * SS * HIDDEN)     // 8M
__device__ __nv_bfloat16 g_qh[NELEM], g_ql[NELEM];
__device__ __nv_bfloat16 g_kh[NELEM], g_kl[NELEM];
__device__ __nv_bfloat16 g_vh[NELEM], g_vl[NELEM];
__device__ __nv_bfloat16 g_Wqh[HIDDEN*HIDDEN], g_Wql[HIDDEN*HIDDEN];
__device__ __nv_bfloat16 g_Wkh[HIDDEN*HIDDEN], g_Wkl[HIDDEN*HIDDEN];
__device__ __nv_bfloat16 g_Wvh[HIDDEN*HIDDEN], g_Wvl[HIDDEN*HIDDEN];
__device__ __nv_bfloat16 g_Woh[HIDDEN*HIDDEN], g_Wol[HIDDEN*HIDDEN];
__device__ __nv_bfloat16 g_Qsh[NELEM], g_Qsl[NELEM];   // [b,h,s,d]
__device__ __nv_bfloat16 g_Ksh[NELEM], g_Ksl[NELEM];   // [b,h,s,d]
__device__ __nv_bfloat16 g_Vth[NELEM], g_Vtl[NELEM];   // [b,h,d,s]
__device__ __nv_bfloat16 g_Ch[NELEM],  g_Cl[NELEM];    // ctx [b,s,1024]

__device__ __forceinline__ uint32_t b2u(__nv_bfloat162 h) {
    uint32_t u; memcpy(&u, &h, 4); return u;
}

__device__ __forceinline__ void mma16816(float* c, const uint32_t* a, const uint32_t* b) {
    asm volatile(
        "mma.sync.aligned.m16n8k16.row.col.f32.bf16.bf16.f32 "
        "{%0,%1,%2,%3}, {%4,%5,%6,%7}, {%8,%9}, {%0,%1,%2,%3};"
        : "+f"(c[0]), "+f"(c[1]), "+f"(c[2]), "+f"(c[3])
        : "r"(a[0]), "r"(a[1]), "r"(a[2]), "r"(a[3]), "r"(b[0]), "r"(b[1]));
}

__device__ __forceinline__ uint32_t smem_u32(const void* p) {
    uint32_t a;
    asm("{ .reg .u64 t; cvta.to.shared.u64 t, %1; cvt.u32.u64 %0, t; }" : "=r"(a) : "l"(p));
    return a;
}

#define CP_ASYNC16(dst, src) \
    asm volatile("cp.async.cg.shared.global [%0], [%1], 16;" :: "r"(dst), "l"(src))
#define CP_COMMIT() asm volatile("cp.async.commit_group;" ::: "memory")
#define CP_WAIT(n)  asm volatile("cp.async.wait_group %0;" :: "n"(n) : "memory")

__device__ __forceinline__ void split_store2(float x, float y,
                                             __nv_bfloat16* H, __nv_bfloat16* L, size_t off) {
    __nv_bfloat162 hp = __floats2bfloat162_rn(x, y);
    float2 hf = __bfloat1622float2(hp);
    __nv_bfloat162 lp = __floats2bfloat162_rn(x - hf.x, y - hf.y);
    *(uint32_t*)(H + off) = b2u(hp);
    *(uint32_t*)(L + off) = b2u(lp);
}

__device__ __forceinline__ void split_store1(float x, __nv_bfloat16* H, __nv_bfloat16* L, size_t off) {
    __nv_bfloat16 h = __float2bfloat16(x);
    H[off] = h;
    L[off] = __float2bfloat16(x - __bfloat162float(h));
}

// ---------------------------------------------------------------------------
// One-time fp32 -> bf16 hi/lo split
// ---------------------------------------------------------------------------
__global__ __launch_bounds__(256)
void split_kernel(const float* __restrict__ X, __nv_bfloat16* __restrict__ Xh,
                  __nv_bfloat16* __restrict__ Xl, int n4)
{
    int i = blockIdx.x * blockDim.x + threadIdx.x;
    if (i >= n4) return;
    float4 v = ((const float4*)X)[i];
    __nv_bfloat162 h01 = __floats2bfloat162_rn(v.x, v.y);
    __nv_bfloat162 h23 = __floats2bfloat162_rn(v.z, v.w);
    float2 f01 = __bfloat1622float2(h01);
    float2 f23 = __bfloat1622float2(h23);
    __nv_bfloat162 l01 = __floats2bfloat162_rn(v.x - f01.x, v.y - f01.y);
    __nv_bfloat162 l23 = __floats2bfloat162_rn(v.z - f23.x, v.w - f23.y);
    ((uint2*)Xh)[i] = make_uint2(b2u(h01), b2u(h23));
    ((uint2*)Xl)[i] = make_uint2(b2u(l01), b2u(l23));
}

// ---------------------------------------------------------------------------
// bf16 split GEMM, cp.async double-buffered, K-chunk 32, 2 CTAs/SM.
// C[m,n] = sum_k A[m,k]*W[n,k] + bias[n]  (3-pass hi/lo accumulation)
// mode 0: split-bf16 out [b,h,s,d]; mode 1: fp32 row-major; mode 2: split Vt
// ---------------------------------------------------------------------------
#define G_RS 80          // bytes per smem row (32 bf16 = 64B data + 16B pad)
#define G_BUF (128 * G_RS)           // 10240 per buffer
#define G_STG (4 * G_BUF)            // 40960 per stage (Ah, Al, Bh, Bl)
#define GEMM_SMEM (2 * G_STG)        // 81920 -> 2 CTAs/SM

__global__ __launch_bounds__(256, 2)
void gemm_bf16_kernel(const __nv_bfloat16* __restrict__ Ah, const __nv_bfloat16* __restrict__ Al,
                      const __nv_bfloat16* __restrict__ Wh, const __nv_bfloat16* __restrict__ Wl,
                      const float* __restrict__ bias, float* __restrict__ outF,
                      __nv_bfloat16* __restrict__ Oh, __nv_bfloat16* __restrict__ Ol, int mode)
{
    extern __shared__ char dsm[];
    const uint32_t su = smem_u32(dsm);
    const int tid = threadIdx.x;
    const int wid = tid >> 5, lane = tid & 31;
    const int lr = lane >> 2, lc = lane & 3;
    const int n0 = blockIdx.x * 128, m0 = blockIdx.y * 128;
    const int wm = (wid >> 2) * 64;
    const int wn = (wid & 3) * 32;

    float acc[4][4][4];
#pragma unroll
    for (int i = 0; i < 4; i++)
#pragma unroll
        for (int j = 0; j < 4; j++)
#pragma unroll
            for (int r = 0; r < 4; r++) acc[i][j][r] = 0.f;

    // stage loader: 4 buffers x 128 rows x 64B; 8 cp.async per thread
#define G_LOAD(s, kt) do { \
    uint32_t base = su + (s) * G_STG; \
    _Pragma("unroll") \
    for (int li = 0; li < 2; li++) { \
        int idx = tid + li * 256; \
        int row = idx >> 2, seg = idx & 3; \
        uint32_t d0 = base + row * G_RS + seg * 16; \
        size_t go = (size_t)row * HIDDEN + (kt) * 32 + seg * 8; \
        CP_ASYNC16(d0,             Ah + (size_t)m0 * HIDDEN + go); \
        CP_ASYNC16(d0 + G_BUF,     Al + (size_t)m0 * HIDDEN + go); \
        CP_ASYNC16(d0 + 2 * G_BUF, Wh + (size_t)n0 * HIDDEN + go); \
        CP_ASYNC16(d0 + 3 * G_BUF, Wl + (size_t)n0 * HIDDEN + go); \
    } \
} while (0)

    G_LOAD(0, 0);
    CP_COMMIT();

    for (int kt = 0; kt < 32; kt++) {
        if (kt < 31) {
            G_LOAD((kt + 1) & 1, kt + 1);
            CP_COMMIT();
            CP_WAIT(1);
        } else {
            CP_WAIT(0);
        }
        __syncthreads();

        char* sAh = dsm + (kt & 1) * G_STG;
        char* sAl = sAh + G_BUF;
        char* sBh = sAh + 2 * G_BUF;
        char* sBl = sAh + 3 * G_BUF;

#pragma unroll
        for (int ks = 0; ks < 2; ks++) {
            const uint32_t kb = ks * 32;
            uint32_t Bhf[4][2], Blf[4][2];
#pragma unroll
            for (int jn = 0; jn < 4; jn++) {
                uint32_t boff = (wn + jn * 8 + lr) * G_RS + kb + lc * 4;
                Bhf[jn][0] = *(const uint32_t*)(sBh + boff);
                Bhf[jn][1] = *(const uint32_t*)(sBh + boff + 16);
                Blf[jn][0] = *(const uint32_t*)(sBl + boff);
                Blf[jn][1] = *(const uint32_t*)(sBl + boff + 16);
            }
#pragma unroll
            for (int i = 0; i < 4; i++) {
                uint32_t aoff = (wm + i * 16 + lr) * G_RS + kb + lc * 4;
                uint32_t Ahf[4], Alf[4];
                Ahf[0] = *(const uint32_t*)(sAh + aoff);
                Ahf[1] = *(const uint32_t*)(sAh + aoff + 8 * G_RS);
                Ahf[2] = *(const uint32_t*)(sAh + aoff + 16);
                Ahf[3] = *(const uint32_t*)(sAh + aoff + 8 * G_RS + 16);
                Alf[0] = *(const uint32_t*)(sAl + aoff);
                Alf[1] = *(const uint32_t*)(sAl + aoff + 8 * G_RS);
                Alf[2] = *(const uint32_t*)(sAl + aoff + 16);
                Alf[3] = *(const uint32_t*)(sAl + aoff + 8 * G_RS + 16);
#pragma unroll
                for (int jn = 0; jn < 4; jn++) {
                    mma16816(acc[i][jn], Ahf, Bhf[jn]);
                    mma16816(acc[i][jn], Ahf, Blf[jn]);
                    mma16816(acc[i][jn], Alf, Bhf[jn]);
                }
            }
        }
        __syncthreads();
    }

#pragma unroll
    for (int i = 0; i < 4; i++) {
#pragma unroll
        for (int jn = 0; jn < 4; jn++) {
            int row = m0 + wm + i * 16 + lr;
            int row8 = row + 8;
            int col = n0 + wn + jn * 8 + lc * 2;
            float x0 = acc[i][jn][0] + bias[col], y0 = acc[i][jn][1] + bias[col + 1];
            float x1 = acc[i][jn][2] + bias[col], y1 = acc[i][jn][3] + bias[col + 1];
            if (mode == 0) {
                int b0_ = row >> 10, s0_ = row & 1023;
                int b1_ = row8 >> 10, s1_ = row8 & 1023;
                int h = col >> 6, d = col & 63;
                split_store2(x0, y0, Oh, Ol, (((size_t)(b0_ * NH + h)) * SS + s0_) * HD + d);
                split_store2(x1, y1, Oh, Ol, (((size_t)(b1_ * NH + h)) * SS + s1_) * HD + d);
            } else if (mode == 1) {
                *(float2*)(outF + (size_t)row * HIDDEN + col) = make_float2(x0, y0);
                *(float2*)(outF + (size_t)row8 * HIDDEN + col) = make_float2(x1, y1);
            } else {
                int b0_ = row >> 10, s0_ = row & 1023;
                int s1_ = row8 & 1023;
                int h = col >> 6, d = col & 63;
                size_t base = (size_t)(b0_ * NH + h) * HD;
                split_store1(x0, Oh, Ol, (base + d) * SS + s0_);
                split_store1(y0, Oh, Ol, (base + d + 1) * SS + s0_);
                split_store1(x1, Oh, Ol, (base + d) * SS + s1_);
                split_store1(y1, Oh, Ol, (base + d + 1) * SS + s1_);
            }
        }
    }
}

// ---------------------------------------------------------------------------
// Tensor-core flash attention, pre-split bf16 inputs, cp.async pipelined K/V.
// 1 CTA per (b, h, 128 q rows); 8 warps x 16 rows; key chunks of 128.
// ---------------------------------------------------------------------------
#define F_QH 0
#define F_QL 18432
#define F_K(s) (36864 + (s) * 36864)    // KL at +18432
#define F_V(s) (110592 + (s) * 34816)   // VL at +17408
#define F_ZS 180224
#define FLASH_SMEM (F_ZS + 1152 * 4)

__global__ __launch_bounds__(256)
void flash_tc_kernel(const __nv_bfloat16* __restrict__ Qhg, const __nv_bfloat16* __restrict__ Qlg,
                     const __nv_bfloat16* __restrict__ Khg, const __nv_bfloat16* __restrict__ Klg,
                     const __nv_bfloat16* __restrict__ Vthg, const __nv_bfloat16* __restrict__ Vtlg,
                     const float* __restrict__ attn_bias, const float* __restrict__ zoom,
                     __nv_bfloat16* __restrict__ Ch, __nv_bfloat16* __restrict__ Cl)
{
    extern __shared__ char sm[];
    const uint32_t su = smem_u32(sm);
    float* zs = (float*)(sm + F_ZS);

    const int tid = threadIdx.x;
    const int wid = tid >> 5, lane = tid & 31;
    const int lr = lane >> 2, lc = lane & 3;
    const int wq = wid * 16;
    const int qt = blockIdx.x, h = blockIdx.y, b = blockIdx.z;
    const int qr0 = qt * 128;

    const __nv_bfloat16* gQh  = Qhg + (((size_t)(b * NH + h)) * SS + qr0) * HD;
    const __nv_bfloat16* gQl  = Qlg + (((size_t)(b * NH + h)) * SS + qr0) * HD;
    const __nv_bfloat16* gKh  = Khg + ((size_t)(b * NH + h)) * SS * HD;
    const __nv_bfloat16* gKl  = Klg + ((size_t)(b * NH + h)) * SS * HD;
    const __nv_bfloat16* gVth = Vthg + ((size_t)(b * NH + h)) * HD * SS;
    const __nv_bfloat16* gVtl = Vtlg + ((size_t)(b * NH + h)) * HD * SS;
    const float* gB = attn_bias + (size_t)b * SS * SS;

#define F_LOAD(s, t0) do { \
    _Pragma("unroll") \
    for (int li = 0; li < 4; li++) { \
        int idx = tid + li * 256; \
        int row = idx >> 3, seg = idx & 7; \
        uint32_t dk = su + F_K(s) + row * 144 + seg * 16; \
        CP_ASYNC16(dk,         gKh + (size_t)((t0) + row) * HD + seg * 8); \
        CP_ASYNC16(dk + 18432, gKl + (size_t)((t0) + row) * HD + seg * 8); \
    } \
    _Pragma("unroll") \
    for (int li = 0; li < 4; li++) { \
        int idx = tid + li * 256; \
        int d = idx >> 4, seg = idx & 15; \
        uint32_t dv = su + F_V(s) + d * 272 + seg * 16; \
        CP_ASYNC16(dv,         gVth + (size_t)d * SS + (t0) + seg * 8); \
        CP_ASYNC16(dv + 17408, gVtl + (size_t)d * SS + (t0) + seg * 8); \
    } \
} while (0)

    F_LOAD(0, 0);
    CP_COMMIT();

    for (int u = tid; u < 1152; u += 256)
        zs[u] = (qr0 + u < 2047) ? zoom[qr0 + u] : 0.f;
#pragma unroll
    for (int li = 0; li < 4; li++) {
        int idx = tid + li * 256;
        int row = idx >> 3, seg = idx & 7;
        *(uint4*)(sm + F_QH + row * 144 + seg * 16) = *(const uint4*)(gQh + row * HD + seg * 8);
        *(uint4*)(sm + F_QL + row * 144 + seg * 16) = *(const uint4*)(gQl + row * HD + seg * 8);
    }

    float accO[8][4];
#pragma unroll
    for (int nt = 0; nt < 8; nt++)
#pragma unroll
        for (int r = 0; r < 4; r++) accO[nt][r] = 0.f;
    float mi0 = -3.0e38f, mi1 = -3.0e38f, li0 = 0.f, li1 = 0.f;

    for (int kt = 0; kt < 8; kt++) {
        const int t0 = kt * 128;
        if (kt < 7) {
            F_LOAD((kt + 1) & 1, t0 + 128);
            CP_COMMIT();
            CP_WAIT(1);
        } else {
            CP_WAIT(0);
        }
        __syncthreads();

        char* sKh = sm + F_K(kt & 1);
        char* sKl = sKh + 18432;
        char* sVh = sm + F_V(kt & 1);
        char* sVl = sVh + 17408;

        // S = Q.K^T : warp computes 16 x 128
        float sc[16][4];
#pragma unroll
        for (int nt = 0; nt < 16; nt++)
#pragma unroll
            for (int r = 0; r < 4; r++) sc[nt][r] = 0.f;

#pragma unroll
        for (int ks = 0; ks < 4; ks++) {
            const uint32_t kb = ks * 32;
            uint32_t aoff = (wq + lr) * 144 + kb + lc * 4;
            uint32_t Ahf[4], Alf[4];
            Ahf[0] = *(const uint32_t*)(sm + F_QH + aoff);
            Ahf[1] = *(const uint32_t*)(sm + F_QH + aoff + 8 * 144);
            Ahf[2] = *(const uint32_t*)(sm + F_QH + aoff + 16);
            Ahf[3] = *(const uint32_t*)(sm + F_QH + aoff + 8 * 144 + 16);
            Alf[0] = *(const uint32_t*)(sm + F_QL + aoff);
            Alf[1] = *(const uint32_t*)(sm + F_QL + aoff + 8 * 144);
            Alf[2] = *(const uint32_t*)(sm + F_QL + aoff + 16);
            Alf[3] = *(const uint32_t*)(sm + F_QL + aoff + 8 * 144 + 16);
#pragma unroll
            for (int nt = 0; nt < 16; nt++) {
                uint32_t boff = (nt * 8 + lr) * 144 + kb + lc * 4;
                uint32_t Bh[2], Bl[2];
                Bh[0] = *(const uint32_t*)(sKh + boff);
                Bh[1] = *(const uint32_t*)(sKh + boff + 16);
                Bl[0] = *(const uint32_t*)(sKl + boff);
                Bl[1] = *(const uint32_t*)(sKl + boff + 16);
                mma16816(sc[nt], Ahf, Bh);
                mma16816(sc[nt], Ahf, Bl);
                mma16816(sc[nt], Alf, Bh);
            }
        }

        // scale + biases, online softmax
        const int row_l0 = wq + lr;
        float mx0 = -3.0e38f, mx1 = -3.0e38f;
#pragma unroll
        for (int nt = 0; nt < 16; nt++) {
            int keyg = t0 + nt * 8 + lc * 2;
            const float* bp = gB + (size_t)(qr0 + row_l0) * SS + keyg;
            float2 bv0 = *(const float2*)bp;
            float2 bv1 = *(const float2*)(bp + 8 * SS);
            int u0 = row_l0 - keyg + 1023;
            sc[nt][0] = fmaf(sc[nt][0], SCALE, bv0.x + zs[u0]);
            sc[nt][1] = fmaf(sc[nt][1], SCALE, bv0.y + zs[u0 - 1]);
            sc[nt][2] = fmaf(sc[nt][2], SCALE, bv1.x + zs[u0 + 8]);
            sc[nt][3] = fmaf(sc[nt][3], SCALE, bv1.y + zs[u0 + 7]);
            mx0 = fmaxf(mx0, fmaxf(sc[nt][0], sc[nt][1]));
            mx1 = fmaxf(mx1, fmaxf(sc[nt][2], sc[nt][3]));
        }
#pragma unroll
        for (int off = 1; off <= 2; off <<= 1) {
            mx0 = fmaxf(mx0, __shfl_xor_sync(0xffffffffu, mx0, off));
            mx1 = fmaxf(mx1, __shfl_xor_sync(0xffffffffu, mx1, off));
        }
        float m0n = fmaxf(mi0, mx0), m1n = fmaxf(mi1, mx1);
        float a0 = __expf(mi0 - m0n), a1 = __expf(mi1 - m1n);
        mi0 = m0n; mi1 = m1n;
        float rs0 = 0.f, rs1 = 0.f;
#pragma unroll
        for (int nt = 0; nt < 16; nt++) {
            sc[nt][0] = __expf(sc[nt][0] - m0n);
            sc[nt][1] = __expf(sc[nt][1] - m0n);
            sc[nt][2] = __expf(sc[nt][2] - m1n);
            sc[nt][3] = __expf(sc[nt][3] - m1n);
            rs0 += sc[nt][0] + sc[nt][1];
            rs1 += sc[nt][2] + sc[nt][3];
        }
#pragma unroll
        for (int off = 1; off <= 2; off <<= 1) {
            rs0 += __shfl_xor_sync(0xffffffffu, rs0, off);
            rs1 += __shfl_xor_sync(0xffffffffu, rs1, off);
        }
        li0 = li0 * a0 + rs0;
        li1 = li1 * a1 + rs1;
#pragma unroll
        for (int nt = 0; nt < 8; nt++) {
            accO[nt][0] *= a0; accO[nt][1] *= a0;
            accO[nt][2] *= a1; accO[nt][3] *= a1;
        }

        // O += P.V  (P in registers: C-frag == A-frag; hi/lo split of P)
#pragma unroll
        for (int g = 0; g < 8; g++) {
            uint32_t Ph[4], Pl[4];
#pragma unroll
            for (int t = 0; t < 2; t++)
#pragma unroll
                for (int r = 0; r < 2; r++) {
                    float x = sc[2 * g + t][2 * r], y = sc[2 * g + t][2 * r + 1];
                    __nv_bfloat162 hp = __floats2bfloat162_rn(x, y);
                    float2 hf = __bfloat1622float2(hp);
                    __nv_bfloat162 lp = __floats2bfloat162_rn(x - hf.x, y - hf.y);
                    Ph[t * 2 + r] = b2u(hp);
                    Pl[t * 2 + r] = b2u(lp);
                }
            const uint32_t kb = g * 32;
#pragma unroll
            for (int nt = 0; nt < 8; nt++) {
                uint32_t boff = (nt * 8 + lr) * 272 + kb + lc * 4;
                uint32_t Bh[2], Bl[2];
                Bh[0] = *(const uint32_t*)(sVh + boff);
                Bh[1] = *(const uint32_t*)(sVh + boff + 16);
                Bl[0] = *(const uint32_t*)(sVl + boff);
                Bl[1] = *(const uint32_t*)(sVl + boff + 16);
                mma16816(accO[nt], Ph, Bh);
                mma16816(accO[nt], Ph, Bl);
                mma16816(accO[nt], Pl, Bh);
            }
        }
        __syncthreads();
    }

    // epilogue: normalize, write split-bf16 Ctx[b][row][h*64+d]
    float inv0 = 1.f / li0, inv1 = 1.f / li1;
    int row0 = qr0 + wq + lr;
#pragma unroll
    for (int nt = 0; nt < 8; nt++) {
        int col = h * HD + nt * 8 + lc * 2;
        split_store2(accO[nt][0] * inv0, accO[nt][1] * inv0, Ch, Cl,
                     ((size_t)(b * SS + row0)) * HIDDEN + col);
        split_store2(accO[nt][2] * inv1, accO[nt][3] * inv1, Ch, Cl,
                     ((size_t)(b * SS + row0 + 8)) * HIDDEN + col);
    }
}

extern "C" void kernel_launch(void* const* d_in, const int* in_sizes, int n_in,
                              void* d_out, int out_size)
{
    const float* q    = (const float*)d_in[0];
    const float* k    = (const float*)d_in[1];
    const float* v    = (const float*)d_in[2];
    const float* ab   = (const float*)d_in[3];
    const float* Wq   = (const float*)d_in[4];
    const float* bq   = (const float*)d_in[5];
    const float* Wk   = (const float*)d_in[6];
    const float* bk   = (const float*)d_in[7];
    const float* Wv   = (const float*)d_in[8];
    const float* bv   = (const float*)d_in[9];
    const float* Wo   = (const float*)d_in[10];
    const float* bo   = (const float*)d_in[11];
    const float* zoom = (const float*)d_in[12];

    __nv_bfloat16 *qh, *ql, *kh, *kl, *vh, *vl;
    __nv_bfloat16 *Wqh, *Wql, *Wkh, *Wkl, *Wvh, *Wvl, *Woh, *Wol;
    __nv_bfloat16 *Qsh, *Qsl, *Ksh, *Ksl, *Vth, *Vtl, *Ch, *Cl;
    cudaGetSymbolAddress((void**)&qh, g_qh);   cudaGetSymbolAddress((void**)&ql, g_ql);
    cudaGetSymbolAddress((void**)&kh, g_kh);   cudaGetSymbolAddress((void**)&kl, g_kl);
    cudaGetSymbolAddress((void**)&vh, g_vh);   cudaGetSymbolAddress((void**)&vl, g_vl);
    cudaGetSymbolAddress((void**)&Wqh, g_Wqh); cudaGetSymbolAddress((void**)&Wql, g_Wql);
    cudaGetSymbolAddress((void**)&Wkh, g_Wkh); cudaGetSymbolAddress((void**)&Wkl, g_Wkl);
    cudaGetSymbolAddress((void**)&Wvh, g_Wvh); cudaGetSymbolAddress((void**)&Wvl, g_Wvl);
    cudaGetSymbolAddress((void**)&Woh, g_Woh); cudaGetSymbolAddress((void**)&Wol, g_Wol);
    cudaGetSymbolAddress((void**)&Qsh, g_Qsh); cudaGetSymbolAddress((void**)&Qsl, g_Qsl);
    cudaGetSymbolAddress((void**)&Ksh, g_Ksh); cudaGetSymbolAddress((void**)&Ksl, g_Ksl);
    cudaGetSymbolAddress((void**)&Vth, g_Vth); cudaGetSymbolAddress((void**)&Vtl, g_Vtl);
    cudaGetSymbolAddress((void**)&Ch, g_Ch);   cudaGetSymbolAddress((void**)&Cl, g_Cl);

    cudaFuncSetAttribute(gemm_bf16_kernel,
                         cudaFuncAttributeMaxDynamicSharedMemorySize, GEMM_SMEM);
    cudaFuncSetAttribute(flash_tc_kernel,
                         cudaFuncAttributeMaxDynamicSharedMemorySize, FLASH_SMEM);

    // one-time splits
    split_kernel<<<NELEM / 1024, 256>>>(q, qh, ql, NELEM / 4);
    split_kernel<<<NELEM / 1024, 256>>>(k, kh, kl, NELEM / 4);
    split_kernel<<<NELEM / 1024, 256>>>(v, vh, vl, NELEM / 4);
    split_kernel<<<HIDDEN * HIDDEN / 1024, 256>>>(Wq, Wqh, Wql, HIDDEN * HIDDEN / 4);
    split_kernel<<<HIDDEN * HIDDEN / 1024, 256>>>(Wk, Wkh, Wkl, HIDDEN * HIDDEN / 4);
    split_kernel<<<HIDDEN * HIDDEN / 1024, 256>>>(Wv, Wvh, Wvl, HIDDEN * HIDDEN / 4);
    split_kernel<<<HIDDEN * HIDDEN / 1024, 256>>>(Wo, Woh, Wol, HIDDEN * HIDDEN / 4);

    dim3 gg(HIDDEN / 128, (BB * SS) / 128);
    gemm_bf16_kernel<<<gg, 256, GEMM_SMEM>>>(qh, ql, Wqh, Wql, bq, nullptr, Qsh, Qsl, 0);
    gemm_bf16_kernel<<<gg, 256, GEMM_SMEM>>>(kh, kl, Wkh, Wkl, bk, nullptr, Ksh, Ksl, 0);
    gemm_bf16_kernel<<<gg, 256, GEMM_SMEM>>>(vh, vl, Wvh, Wvl, bv, nullptr, Vth, Vtl, 2);

    dim3 gf(SS / 128, NH, BB);
    flash_tc_kernel<<<gf, 256, FLASH_SMEM>>>(Qsh, Qsl, Ksh, Ksl, Vth, Vtl, ab, zoom, Ch, Cl);

    gemm_bf16_kernel<<<gg, 256, GEMM_SMEM>>>(Ch, Cl, Woh, Wol, bo, (float*)d_out,
                                             nullptr, nullptr, 1);
}